// round 9
// baseline (speedup 1.0000x reference)
#include <cuda_runtime.h>
#include <math.h>

// ---------------------------------------------------------------------------
// VariableAnnuity PNL — single fused kernel.
//
// inputs: d_in[0] spots f32 [61*65536], d_in[1] W1 [2*128], d_in[2] b1 [128],
//         d_in[3] W2 [128*128], d_in[4] b2 [128], d_in[5] W3 [128], d_in[6] b3 [1]
// output: pnl f32 [65536]
//
// R8: two launches cost ~13us of fixed overhead -> fuse. Blocks 0..119 build
// the per-step delta table (analytic float-bit-space grid, FFMA2 inner
// product); blocks 120..631 are main blocks that overlap the build by
// streaming their spots into smem, then spin on a release/acquire counter
// and finish with pure LDS + table-L1 + FMA work. Counters self-reset for
// graph replay. Builders (bids 0..119) are wave-1 resident -> no deadlock.
// ---------------------------------------------------------------------------

#define NPATH   65536
#define NSTEPS  60
#define HID     128
#define NTAB    128
#define NB      120                 // builder blocks (2 per step)
#define NMAIN   512                 // main blocks (128 paths x 2 chunks each)
#define SMEM_BYTES 35840

#define F_DT    (1.0f / 12.0f)
#define F_FEE   0.0196f
#define F_LAM   0.01f
#define F_TEXP  5.0f
#define F_PRIN  100.0f

__device__ float g_tab[NSTEPS][NTAB];
__device__ int   g_ready;           // builders done counter (self-resetting)
__device__ int   g_done;            // mains done counter   (self-resetting)

// packed f32x2 helpers (Blackwell FFMA2)
__device__ __forceinline__ unsigned long long pack2(float x) {
    unsigned long long r;
    asm("mov.b64 %0, {%1, %1};" : "=l"(r) : "f"(x));
    return r;
}
__device__ __forceinline__ unsigned long long fma2(unsigned long long a,
                                                   unsigned long long b,
                                                   unsigned long long c) {
    unsigned long long d;
    asm("fma.rn.f32x2 %0, %1, %2, %3;" : "=l"(d) : "l"(a), "l"(b), "l"(c));
    return d;
}
__device__ __forceinline__ void unpack2(unsigned long long v, float& lo, float& hi) {
    asm("mov.b64 {%0, %1}, %2;" : "=f"(lo), "=f"(hi) : "l"(v));
}

// Analytic per-step grid in float-bit space (log-spot is N(-0.02t, (0.2√t)^2);
// float bits are monotone ~affine in log s). __noinline__ so builder and main
// use one compiled instance -> bitwise-identical grid.
__device__ __noinline__ void grid_params(int i, int& B0, int& m,
                                         float& smin, float& smax, float& inv)
{
    const float t   = (float)i * F_DT;
    const float sig = 0.2f * sqrtf(t);
    const float mu  = -0.02f * t;
    const float lo  = expf(mu - 7.0f * sig);
    const float hi  = expf(mu + 7.0f * sig);
    const int   rng = __float_as_int(hi) - __float_as_int(lo);
    const int   q   = (rng + (NTAB - 2)) / (NTAB - 1);
    m = (q <= 1) ? 0 : (32 - __clz(q - 1));
    const int Bc = __float_as_int(expf(mu));
    B0 = Bc - (((NTAB - 1) << m) >> 1);
    smin = __int_as_float(B0);
    smax = __int_as_float(B0 + ((NTAB - 1) << m));
    inv  = 1.0f / (float)(1 << m);
}

// ---------------------------------------------------------------------------
__global__ void __launch_bounds__(256) va_fused_kernel(
    const float* __restrict__ spots,
    const float* __restrict__ W1, const float* __restrict__ b1,
    const float* __restrict__ W2, const float* __restrict__ b2,
    const float* __restrict__ W3, const float* __restrict__ b3,
    float* __restrict__ out)
{
    extern __shared__ float sm[];
    const int tid = threadIdx.x;

    if (blockIdx.x < NB) {
        // =============== BUILDER BLOCK: (step, entry-half) ===============
        float* W2s   = sm;                  // [64][128]  32 KB (one k-half)
        float* aS    = W2s + 64 * HID;      // [128]
        float* cS    = aS + HID;
        float* b2S   = cS + HID;
        float* w3S   = b2S + HID;
        float* partS = w3S + HID;           // [4][64]

        const int step  = blockIdx.x >> 1;
        const int ehalf = blockIdx.x & 1;
        const float t = (float)step * F_DT;

        int B0, m; float smin, smax, invu;
        grid_params(step, B0, m, smin, smax, invu);

        if (tid < HID) {
            aS[tid]  = W1[tid];
            cS[tid]  = t * W1[HID + tid] + b1[tid];
            b2S[tid] = b2[tid];
            w3S[tid] = W3[tid];
        }

        const int entry = tid & 63;
        const int jq    = tid >> 6;
        const float spot = __int_as_float(B0 + ((ehalf * 64 + entry) << m));

        unsigned long long acc[16];
        #pragma unroll
        for (int q = 0; q < 16; q++) acc[q] = 0ull;

        #pragma unroll 1
        for (int h = 0; h < 2; h++) {
            __syncthreads();
            const float4* src = reinterpret_cast<const float4*>(W2) + h * 2048;
            float4* dst = reinterpret_cast<float4*>(W2s);
            #pragma unroll
            for (int q = 0; q < 8; q++)
                dst[q * 256 + tid] = src[q * 256 + tid];
            __syncthreads();

            #pragma unroll 1
            for (int kk = 0; kk < 64; kk++) {
                const int k = h * 64 + kk;
                const float h1 = fmaxf(fmaf(spot, aS[k], cS[k]), 0.0f);
                if (__ballot_sync(0xffffffffu, h1 > 0.0f)) {   // uniform skip
                    const unsigned long long hp = pack2(h1);
                    const ulonglong2* wr = reinterpret_cast<const ulonglong2*>(
                        &W2s[kk * HID + jq * 32]);
                    #pragma unroll
                    for (int q = 0; q < 8; q++) {
                        ulonglong2 w = wr[q];
                        acc[2 * q]     = fma2(hp, w.x, acc[2 * q]);
                        acc[2 * q + 1] = fma2(hp, w.y, acc[2 * q + 1]);
                    }
                }
            }
        }

        float p = 0.0f;
        #pragma unroll
        for (int q = 0; q < 16; q++) {
            float lo, hi;
            unpack2(acc[q], lo, hi);
            const int j0 = jq * 32 + 2 * q;
            p = fmaf(fmaxf(lo + b2S[j0],     0.0f), w3S[j0],     p);
            p = fmaf(fmaxf(hi + b2S[j0 + 1], 0.0f), w3S[j0 + 1], p);
        }
        partS[jq * 64 + entry] = p;
        __syncthreads();

        if (tid < 64) {
            const float o = b3[0] + ((partS[tid] + partS[64 + tid])
                                   + (partS[128 + tid] + partS[192 + tid]));
            const float d0 = -(o * o);
            const float d1 = d0 * fminf(expf(-0.01f * d0), 1.0f);
            const float scale = (1.0f - expf(-F_LAM * (F_TEXP - t))) * F_PRIN;
            g_tab[step][ehalf * 64 + tid] = d1 * scale;
        }
        __syncthreads();
        if (tid == 0) {
            __threadfence();
            atomicAdd(&g_ready, 1);   // release this block's table half
        }
    } else {
        // ================= MAIN BLOCK: 128 paths x 2 chunks ==============
        float*  spotsS = sm;                                  // [2*30][128]
        float4* c0S = reinterpret_cast<float4*>(spotsS + 2 * 30 * 128);  // [60]
        float4* c1S = c0S + NSTEPS;                                      // [60]
        float*  part = reinterpret_cast<float*>(c1S + NSTEPS);           // [256]

        const int mbid  = blockIdx.x - NB;
        const int chunk = tid >> 7;          // 2 chunks of 30 steps
        const int pl    = tid & 127;
        const int p     = mbid * 128 + pl;
        const int ibase = chunk * 30;

        // per-step constants (overlaps build)
        if (tid < NSTEPS) {
            const float t = (float)tid * F_DT;
            const float eFee = expf(-F_FEE * t);
            const float eLam = expf(-F_LAM * t);
            int B0, m; float smin, smax, invu;
            grid_params(tid, B0, m, smin, smax, invu);
            c0S[tid] = make_float4(smin, smax, invu, __int_as_float(B0));
            c1S[tid] = make_float4(F_FEE * F_DT * F_PRIN * eFee * eLam,  // A
                                   F_LAM * F_DT * eLam * F_PRIN * eFee,  // B
                                   1.0f / eFee,                          // C
                                   0.0f);
        }

        // stream this block's spot slices into smem (overlaps build)
        const float s0 = spots[(size_t)ibase * NPATH + p];
        #pragma unroll
        for (int j = 0; j < 30; j++)
            spotsS[(chunk * 30 + j) * 128 + pl] =
                spots[(size_t)(ibase + 1 + j) * NPATH + p];

        __syncthreads();   // smem spots + consts complete

        // wait for all 120 builder halves
        if (tid == 0) {
            while (atomicAdd(&g_ready, 0) < NB) __nanosleep(128);
            __threadfence();
        }
        __syncthreads();

        float s = s0;
        float pnl = 0.0f;
        #pragma unroll
        for (int j = 0; j < 30; j++) {
            const int i = ibase + j;
            const float4 k0 = c0S[i];
            const float4 k1 = c1S[i];
            const float snext = spotsS[(chunk * 30 + j) * 128 + pl];

            // table lookup in bit space
            const float sc = fminf(fmaxf(s, k0.x), k0.y);
            const int   ub = __float_as_int(sc) - __float_as_int(k0.w);
            const float u  = (float)ub * k0.z;
            int i0 = min((int)u, NTAB - 2);
            const float f  = u - (float)i0;
            const float t0 = __ldg(&g_tab[i][i0]);
            const float t1 = __ldg(&g_tab[i][i0 + 1]);
            const float delta = fmaf(f, t1 - t0, t0);

            // fee - payout = A*s - B*max(C - s, 0)
            const float pm = fmaxf(k1.z - s, 0.0f);
            pnl = fmaf(s, k1.x, pnl);
            pnl = fmaf(-k1.y, pm, pnl);
            pnl = fmaf(delta, snext - s, pnl);
            s = snext;
        }

        part[tid] = pnl;
        __syncthreads();
        if (tid < 128)
            out[mbid * 128 + tid] = part[tid] + part[tid + 128];
        __syncthreads();

        // self-reset counters for graph replay (last main block)
        if (tid == 0) {
            const int old = atomicAdd(&g_done, 1);
            if (old == NMAIN - 1) {
                atomicExch(&g_ready, 0);
                atomicExch(&g_done, 0);
            }
        }
    }
}

// ---------------------------------------------------------------------------
extern "C" void kernel_launch(void* const* d_in, const int* in_sizes, int n_in,
                              void* d_out, int out_size) {
    (void)in_sizes; (void)n_in; (void)out_size;
    const float* spots = (const float*)d_in[0];
    const float* W1    = (const float*)d_in[1];
    const float* b1    = (const float*)d_in[2];
    const float* W2    = (const float*)d_in[3];
    const float* b2    = (const float*)d_in[4];
    const float* W3    = (const float*)d_in[5];
    const float* b3    = (const float*)d_in[6];
    float* out = (float*)d_out;

    va_fused_kernel<<<NB + NMAIN, 256, SMEM_BYTES>>>(
        spots, W1, b1, W2, b2, W3, b3, out);
}

// round 10
// speedup vs baseline: 1.0480x; 1.0480x over previous
#include <cuda_runtime.h>
#include <math.h>

// ---------------------------------------------------------------------------
// VariableAnnuity PNL — two kernels + PDL overlap.
//
// inputs: d_in[0] spots f32 [61*65536], d_in[1] W1 [2*128], d_in[2] b1 [128],
//         d_in[3] W2 [128*128], d_in[4] b2 [128], d_in[5] W3 [128], d_in[6] b3 [1]
// output: pnl f32 [65536]
//
// R9: R8's single-kernel fusion regressed (spin-wait + builder/main SM
// contention) -> revert to two kernels, overlap them with programmatic
// dependent launch instead. Build (primary) triggers launch completion at
// block start; main (secondary) runs its prelude (per-step constants, first
// spot loads) then cudaGridDependencySynchronize() before touching the table.
// Main is 4-path float4 vectorized: thread = (path-group, chunk), 4 pnl
// chains per thread, 15 steps each, smem reduce over 4 chunks.
// ---------------------------------------------------------------------------

#define NPATH   65536
#define NP4     (NPATH / 4)        // 16384 float4 path-groups
#define NSTEPS  60
#define HID     128
#define NTAB    128

#define F_DT    (1.0f / 12.0f)
#define F_FEE   0.0196f
#define F_LAM   0.01f
#define F_TEXP  5.0f
#define F_PRIN  100.0f

__device__ float g_tab[NSTEPS][NTAB];

// packed f32x2 helpers (Blackwell FFMA2)
__device__ __forceinline__ unsigned long long pack2(float x) {
    unsigned long long r;
    asm("mov.b64 %0, {%1, %1};" : "=l"(r) : "f"(x));
    return r;
}
__device__ __forceinline__ unsigned long long fma2(unsigned long long a,
                                                   unsigned long long b,
                                                   unsigned long long c) {
    unsigned long long d;
    asm("fma.rn.f32x2 %0, %1, %2, %3;" : "=l"(d) : "l"(a), "l"(b), "l"(c));
    return d;
}
__device__ __forceinline__ void unpack2(unsigned long long v, float& lo, float& hi) {
    asm("mov.b64 {%0, %1}, %2;" : "=f"(lo), "=f"(hi) : "l"(v));
}

// Analytic per-step grid in float-bit space. __noinline__ -> one compiled
// instance shared by both kernels (bitwise-identical grid).
__device__ __noinline__ void grid_params(int i, int& B0, int& m,
                                         float& smin, float& smax, float& inv)
{
    const float t   = (float)i * F_DT;
    const float sig = 0.2f * sqrtf(t);
    const float mu  = -0.02f * t;
    const float lo  = expf(mu - 7.0f * sig);
    const float hi  = expf(mu + 7.0f * sig);
    const int   rng = __float_as_int(hi) - __float_as_int(lo);
    const int   q   = (rng + (NTAB - 2)) / (NTAB - 1);
    m = (q <= 1) ? 0 : (32 - __clz(q - 1));
    const int Bc = __float_as_int(expf(mu));
    B0 = Bc - (((NTAB - 1) << m) >> 1);
    smin = __int_as_float(B0);
    smax = __int_as_float(B0 + ((NTAB - 1) << m));
    inv  = 1.0f / (float)(1 << m);
}

// ---------------------------------------------------------------------------
// Kernel 1 (primary): build delta table. grid = NSTEPS*2 (step, entry-half),
// 256 thr = 64 entries x 4 j-quarters. FFMA2 inner product, warp-uniform
// ReLU skip. Triggers programmatic launch of the main kernel at block start.
// ---------------------------------------------------------------------------
__global__ void __launch_bounds__(256) va_build_kernel(
    const float* __restrict__ W1, const float* __restrict__ b1,
    const float* __restrict__ W2, const float* __restrict__ b2,
    const float* __restrict__ W3, const float* __restrict__ b3)
{
    if (threadIdx.x == 0) cudaTriggerProgrammaticLaunchCompletion();

    __shared__ float W2s[64][HID];     // 32 KB k-half
    __shared__ float aS[HID], cS[HID], b2S[HID], w3S[HID];
    __shared__ float partS[4][64];

    const int tid   = threadIdx.x;
    const int step  = blockIdx.x >> 1;
    const int ehalf = blockIdx.x & 1;
    const float t = (float)step * F_DT;

    int B0, m; float smin, smax, invu;
    grid_params(step, B0, m, smin, smax, invu);

    if (tid < HID) {
        aS[tid]  = W1[tid];
        cS[tid]  = t * W1[HID + tid] + b1[tid];
        b2S[tid] = b2[tid];
        w3S[tid] = W3[tid];
    }

    const int entry = tid & 63;
    const int jq    = tid >> 6;
    const float spot = __int_as_float(B0 + ((ehalf * 64 + entry) << m));

    unsigned long long acc[16];
    #pragma unroll
    for (int q = 0; q < 16; q++) acc[q] = 0ull;

    #pragma unroll 1
    for (int h = 0; h < 2; h++) {
        __syncthreads();
        const float4* src = reinterpret_cast<const float4*>(W2) + h * 2048;
        float4* dst = reinterpret_cast<float4*>(&W2s[0][0]);
        #pragma unroll
        for (int q = 0; q < 8; q++)
            dst[q * 256 + tid] = src[q * 256 + tid];
        __syncthreads();

        #pragma unroll 1
        for (int kk = 0; kk < 64; kk++) {
            const int k = h * 64 + kk;
            const float h1 = fmaxf(fmaf(spot, aS[k], cS[k]), 0.0f);
            if (__ballot_sync(0xffffffffu, h1 > 0.0f)) {   // warp-uniform skip
                const unsigned long long hp = pack2(h1);
                const ulonglong2* wr =
                    reinterpret_cast<const ulonglong2*>(&W2s[kk][jq * 32]);
                #pragma unroll
                for (int q = 0; q < 8; q++) {
                    ulonglong2 w = wr[q];
                    acc[2 * q]     = fma2(hp, w.x, acc[2 * q]);
                    acc[2 * q + 1] = fma2(hp, w.y, acc[2 * q + 1]);
                }
            }
        }
    }

    float p = 0.0f;
    #pragma unroll
    for (int q = 0; q < 16; q++) {
        float lo, hi;
        unpack2(acc[q], lo, hi);
        const int j0 = jq * 32 + 2 * q;
        p = fmaf(fmaxf(lo + b2S[j0],     0.0f), w3S[j0],     p);
        p = fmaf(fmaxf(hi + b2S[j0 + 1], 0.0f), w3S[j0 + 1], p);
    }
    partS[jq][entry] = p;
    __syncthreads();

    if (tid < 64) {
        const float o = b3[0] + ((partS[0][tid] + partS[1][tid])
                               + (partS[2][tid] + partS[3][tid]));
        const float d0 = -(o * o);
        const float d1 = d0 * fminf(expf(-0.01f * d0), 1.0f);
        const float scale = (1.0f - expf(-F_LAM * (F_TEXP - t))) * F_PRIN;
        g_tab[step][ehalf * 64 + tid] = d1 * scale;
    }
}

// ---------------------------------------------------------------------------
// one lane of the PNL step
// ---------------------------------------------------------------------------
__device__ __forceinline__ float lane_step(float s, float nx,
                                           float4 k0, float4 k1,
                                           const float* __restrict__ tabrow)
{
    const float sc = fminf(fmaxf(s, k0.x), k0.y);
    const int   ub = __float_as_int(sc) - __float_as_int(k0.w);
    const float u  = (float)ub * k0.z;
    const int   i0 = min((int)u, NTAB - 2);
    const float f  = u - (float)i0;
    const float t0 = __ldg(tabrow + i0);
    const float t1 = __ldg(tabrow + i0 + 1);
    const float delta = fmaf(f, t1 - t0, t0);
    const float pm = fmaxf(k1.z - s, 0.0f);                 // max(C - s, 0)
    return fmaf(s, k1.x, fmaf(-k1.y, pm, delta * (nx - s)));
}

// ---------------------------------------------------------------------------
// Kernel 2 (secondary): main PNL pass. grid = NP4/64 = 256 blocks, 256 thr =
// 64 path-groups (float4 = 4 paths) x 4 chunks (15 steps). Prelude overlaps
// the build via PDL; gridsync before the table loop.
// ---------------------------------------------------------------------------
__global__ void __launch_bounds__(256) va_main_kernel(
    const float4* __restrict__ sp4, float4* __restrict__ out4)
{
    __shared__ float4 c0S[NSTEPS];   // (smin, smax, inv, bitcast B0)
    __shared__ float4 c1S[NSTEPS];   // (A, B, C, 0)
    __shared__ float4 partS[256];
    const int tid = threadIdx.x;

    if (tid < NSTEPS) {
        const float t = (float)tid * F_DT;
        const float eFee = expf(-F_FEE * t);
        const float eLam = expf(-F_LAM * t);
        int B0, m; float smin, smax, invu;
        grid_params(tid, B0, m, smin, smax, invu);
        c0S[tid] = make_float4(smin, smax, invu, __int_as_float(B0));
        c1S[tid] = make_float4(F_FEE * F_DT * F_PRIN * eFee * eLam,  // A
                               F_LAM * F_DT * eLam * F_PRIN * eFee,  // B
                               1.0f / eFee,                          // C
                               0.0f);
    }

    const int pg    = tid & 63;
    const int chunk = tid >> 6;
    const int p4    = blockIdx.x * 64 + pg;
    const int ibase = chunk * 15;

    float4 s = sp4[(size_t)ibase * NP4 + p4];   // prelude load (overlaps build)
    __syncthreads();                            // consts ready

    cudaGridDependencySynchronize();            // wait for the table

    float4 pnl = make_float4(0.0f, 0.0f, 0.0f, 0.0f);
    #pragma unroll
    for (int j = 0; j < 15; j++) {
        const int i = ibase + j;
        const float4 nx = sp4[(size_t)(i + 1) * NP4 + p4];
        const float4 k0 = c0S[i];
        const float4 k1 = c1S[i];
        const float* tr = &g_tab[i][0];
        pnl.x += lane_step(s.x, nx.x, k0, k1, tr);
        pnl.y += lane_step(s.y, nx.y, k0, k1, tr);
        pnl.z += lane_step(s.z, nx.z, k0, k1, tr);
        pnl.w += lane_step(s.w, nx.w, k0, k1, tr);
        s = nx;
    }

    partS[tid] = pnl;
    __syncthreads();
    if (tid < 64) {
        const float4 a = partS[tid];
        const float4 b = partS[tid + 64];
        const float4 c = partS[tid + 128];
        const float4 d = partS[tid + 192];
        out4[blockIdx.x * 64 + tid] =
            make_float4(((a.x + b.x) + c.x) + d.x,
                        ((a.y + b.y) + c.y) + d.y,
                        ((a.z + b.z) + c.z) + d.z,
                        ((a.w + b.w) + c.w) + d.w);
    }
}

// ---------------------------------------------------------------------------
extern "C" void kernel_launch(void* const* d_in, const int* in_sizes, int n_in,
                              void* d_out, int out_size) {
    (void)in_sizes; (void)n_in; (void)out_size;
    const float*  spots = (const float*)d_in[0];
    const float*  W1    = (const float*)d_in[1];
    const float*  b1    = (const float*)d_in[2];
    const float*  W2    = (const float*)d_in[3];
    const float*  b2    = (const float*)d_in[4];
    const float*  W3    = (const float*)d_in[5];
    const float*  b3    = (const float*)d_in[6];
    const float4* sp4   = (const float4*)spots;
    float4*       out4  = (float4*)d_out;

    va_build_kernel<<<NSTEPS * 2, 256>>>(W1, b1, W2, b2, W3, b3);

    // PDL launch of the main kernel; falls back to a plain serial launch.
    cudaLaunchConfig_t cfg = {};
    cfg.gridDim  = dim3(NP4 / 64, 1, 1);
    cfg.blockDim = dim3(256, 1, 1);
    cfg.dynamicSmemBytes = 0;
    cfg.stream = 0;
    cudaLaunchAttribute attr[1];
    attr[0].id = cudaLaunchAttributeProgrammaticStreamSerialization;
    attr[0].val.programmaticStreamSerializationAllowed = 1;
    cfg.attrs = attr;
    cfg.numAttrs = 1;
    cudaError_t err = cudaLaunchKernelEx(&cfg, va_main_kernel, sp4, out4);
    if (err != cudaSuccess) {
        (void)cudaGetLastError();   // clear sticky error
        va_main_kernel<<<NP4 / 64, 256>>>(sp4, out4);
    }
}